// round 6
// baseline (speedup 1.0000x reference)
#include <cuda_runtime.h>
#include <math.h>
#include <stddef.h>

#define EPSR 1e-8f
// 1/sqrt(1 + 1e-5)
#define BN_SCALE 0.99999500003749969f
#define LOG2PI 1.8378770664093454836f

// ---------------------------------------------------------------------------
// Scratch buffers (device globals; no allocation allowed)
// ---------------------------------------------------------------------------
__device__ float g_buf1 [32*256*14*14];
__device__ float g_bufA [32*16*12*12];
__device__ float g_bufP [32*256*12*12];
__device__ float g_bufA2[32*16*6*6];
__device__ float g_bufP2[32*256*6*6];
__device__ float g_bufA3[32*16*6*6];
__device__ float g_bufP3[32*256*6*6];
__device__ float g_bufFC[32*25*10];

// ---------------------------------------------------------------------------
// conv1: x(32,3,32,32) * w(256,3,5,5) stride2 VALID -> (32,256,14,14), + bn
// ---------------------------------------------------------------------------
__global__ void conv1_kernel(const float* __restrict__ x,
                             const float* __restrict__ w,
                             const float* __restrict__ g,
                             const float* __restrict__ b,
                             float* __restrict__ out)
{
    __shared__ float sIn[3*32*33];
    const int n = blockIdx.x, cot = blockIdx.y;
    const int tid = threadIdx.x;

    for (int idx = tid; idx < 3*32*32; idx += 224) {
        int ci = idx >> 10, rem = idx & 1023, r = rem >> 5, c = rem & 31;
        sIn[(ci*32 + r)*33 + c] = x[n*3072 + idx];
    }
    __syncthreads();

    const int co_l = tid / 14, oy = tid % 14;
    const int co = cot*16 + co_l;

    float acc[14];
#pragma unroll
    for (int i = 0; i < 14; i++) acc[i] = 0.f;

    const float* wp = w + co*75;
#pragma unroll
    for (int ci = 0; ci < 3; ci++) {
#pragma unroll
        for (int kh = 0; kh < 5; kh++) {
            const float* row = sIn + (ci*32 + oy*2 + kh)*33;
#pragma unroll
            for (int kw = 0; kw < 5; kw++) {
                float wv = wp[(ci*5 + kh)*5 + kw];
#pragma unroll
                for (int ox = 0; ox < 14; ox++)
                    acc[ox] = fmaf(wv, row[ox*2 + kw], acc[ox]);
            }
        }
    }
    const float sc = BN_SCALE * g[co], bi = b[co];
    float* op = out + (((size_t)n*256 + co)*14 + oy)*14;
#pragma unroll
    for (int ox = 0; ox < 14; ox++) op[ox] = acc[ox]*sc + bi;
}

// ---------------------------------------------------------------------------
// 3x3 conv over buf1 (N,CI=256,14,14) -> (N,CO,12,12), + bn (+sigmoid)
// ---------------------------------------------------------------------------
template<bool SIG, int NCO>
__global__ void conv3_kernel(const float* __restrict__ in,
                             const float* __restrict__ w,
                             const float* __restrict__ g,
                             const float* __restrict__ bb,
                             float* __restrict__ out,
                             int CI, int CO)
{
    extern __shared__ float sIn[];   // 64*196
    const int n = blockIdx.x;
    const int tid = threadIdx.x;
    const int co_l = tid / 12, oy = tid % 12;
    const int co0 = blockIdx.y*(16*NCO) + co_l;

    float acc[NCO][12];
#pragma unroll
    for (int q = 0; q < NCO; q++)
#pragma unroll
        for (int i = 0; i < 12; i++) acc[q][i] = 0.f;

    for (int ci0 = 0; ci0 < CI; ci0 += 64) {
        __syncthreads();
        for (int idx = tid; idx < 64*196; idx += 192)
            sIn[idx] = in[((size_t)n*CI + ci0)*196 + idx];
        __syncthreads();

        for (int c = 0; c < 64; c++) {
            float w9[NCO][9];
#pragma unroll
            for (int q = 0; q < NCO; q++) {
                const float* wp = w + ((size_t)(co0 + q*16)*CI + ci0 + c)*9;
#pragma unroll
                for (int i = 0; i < 9; i++) w9[q][i] = wp[i];
            }
#pragma unroll
            for (int kh = 0; kh < 3; kh++) {
                const float* row = sIn + (c*14 + oy + kh)*14;
                float rv[14];
#pragma unroll
                for (int i = 0; i < 14; i++) rv[i] = row[i];
#pragma unroll
                for (int kw = 0; kw < 3; kw++) {
#pragma unroll
                    for (int q = 0; q < NCO; q++) {
                        float wv = w9[q][kh*3 + kw];
#pragma unroll
                        for (int ox = 0; ox < 12; ox++)
                            acc[q][ox] = fmaf(wv, rv[ox + kw], acc[q][ox]);
                    }
                }
            }
        }
    }
#pragma unroll
    for (int q = 0; q < NCO; q++) {
        const int co = co0 + q*16;
        const float sc = BN_SCALE * g[co], bi = bb[co];
        float* op = out + (((size_t)n*CO + co)*12 + oy)*12;
#pragma unroll
        for (int ox = 0; ox < 12; ox++) {
            float v = acc[q][ox]*sc + bi;
            if (SIG) v = 1.0f / (1.0f + __expf(-v));
            op[ox] = v;
        }
    }
}

// ---------------------------------------------------------------------------
// EM routing v6 (BB=16, PS=16): register-resident votes.
//   Warp w owns k-chunk [w*CH, (w+1)*CH). Lane = (j=lane&15, ph=lane>>4).
//   Each thread holds vr[CH][8]: votes for (its j, its 8 p's) over CH k's,
//   and rs[CH] = r*a_in in registers. Smem only carries moment partials.
// ---------------------------------------------------------------------------
template<int NT, int A_, int KS, int STR, int PD, int IH, int OH>
__global__ __launch_bounds__(NT, 1)
void em_reg_kernel(const float* __restrict__ aIn,
                   const float* __restrict__ poseIn,
                   const float* __restrict__ Wm,    // (KS*KS*A_, 16, 4,4)
                   const float* __restrict__ bu,
                   const float* __restrict__ ba,
                   const float* __restrict__ bng,
                   const float* __restrict__ bnb,
                   float* __restrict__ aOut,
                   float* __restrict__ poseOut)
{
    constexpr int PS   = 16, BB = 16, BBPS = 256;
    constexpr int KK   = KS*KS;
    constexpr int KKA  = KK*A_;
    constexpr int NW   = NT/32;
    constexpr int CH   = KKA/NW;              // must divide exactly
    static_assert(CH*NW == KKA, "CH split");
    static_assert(KKA*PS <= NW*BBPS, "spt alias fits in pbm");

    __shared__ float pbm[NW*BBPS];            // moment partials (mu); spt alias
    __shared__ float pbs[NW*BBPS];            // moment partials (v^2)
    __shared__ float smu[BBPS];
    __shared__ float ssg[BBPS];               // 1/(2 sigma)
    __shared__ float sa_s[KKA];
    __shared__ float pA[NW*16];
    __shared__ float srs[16], sinv[16], sS[16], sao[16], sbia[16];

    float* spt = pbm;                         // pose patch (phase 0 only)

    const int lidx = blockIdx.x;
    const int oy = lidx / OH, ox = lidx % OH;
    const int n  = blockIdx.y;
    const int tid  = threadIdx.x;
    const int wid  = tid >> 5;
    const int lane = tid & 31;
    const int j    = lane & 15;
    const int ph   = lane >> 4;
    const int k0   = wid*CH;

    // ---- Phase 0a: gather pose patch + a_in (zero-padded) ----
    for (int t = tid; t < KKA*PS; t += NT) {
        const int k = t / PS, p = t % PS;
        const int kk = k / A_, ai = k % A_;
        const int ki = kk / KS, kj = kk % KS;
        const int iy = oy*STR + ki - PD, ix = ox*STR + kj - PD;
        float v = 0.f;
        if (iy >= 0 && iy < IH && ix >= 0 && ix < IH)
            v = poseIn[(((size_t)n*A_*PS + ai*PS + p)*IH + iy)*IH + ix];
        spt[k*PS + p] = v;
    }
    for (int k = tid; k < KKA; k += NT) {
        const int kk = k / A_, ai = k % A_;
        const int ki = kk / KS, kj = kk % KS;
        const int iy = oy*STR + ki - PD, ix = ox*STR + kj - PD;
        float v = 0.f;
        if (iy >= 0 && iy < IH && ix >= 0 && ix < IH)
            v = aIn[(((size_t)n*A_ + ai)*IH + iy)*IH + ix];
        sa_s[k] = v;
    }
    __syncthreads();

    // ---- Phase 0b: votes into registers; rs = a_in/16 init ----
    float vr[CH][8];
    float rs[CH];
#pragma unroll
    for (int i = 0; i < CH; i++) {
        const int k = k0 + i;
        const float4 pa = *(const float4*)(spt + k*PS + ph*8);     // row xi=2ph
        const float4 pb = *(const float4*)(spt + k*PS + ph*8 + 4); // row xi=2ph+1
        const float* wj = Wm + ((size_t)k*16 + j)*16;
        const float4 w0 = *(const float4*)(wj);
        const float4 w1 = *(const float4*)(wj + 4);
        const float4 w2 = *(const float4*)(wj + 8);
        const float4 w3 = *(const float4*)(wj + 12);
        vr[i][0] = fmaf(pa.x,w0.x, fmaf(pa.y,w1.x, fmaf(pa.z,w2.x, pa.w*w3.x)));
        vr[i][1] = fmaf(pa.x,w0.y, fmaf(pa.y,w1.y, fmaf(pa.z,w2.y, pa.w*w3.y)));
        vr[i][2] = fmaf(pa.x,w0.z, fmaf(pa.y,w1.z, fmaf(pa.z,w2.z, pa.w*w3.z)));
        vr[i][3] = fmaf(pa.x,w0.w, fmaf(pa.y,w1.w, fmaf(pa.z,w2.w, pa.w*w3.w)));
        vr[i][4] = fmaf(pb.x,w0.x, fmaf(pb.y,w1.x, fmaf(pb.z,w2.x, pb.w*w3.x)));
        vr[i][5] = fmaf(pb.x,w0.y, fmaf(pb.y,w1.y, fmaf(pb.z,w2.y, pb.w*w3.y)));
        vr[i][6] = fmaf(pb.x,w0.z, fmaf(pb.y,w1.z, fmaf(pb.z,w2.z, pb.w*w3.z)));
        vr[i][7] = fmaf(pb.x,w0.w, fmaf(pb.y,w1.w, fmaf(pb.z,w2.w, pb.w*w3.w)));
        rs[i] = sa_s[k] * (1.0f/16.0f);
    }

    float p95 = 1.0f;
    for (int it = 0; it < 3; it++) {
        p95 *= 0.95f;
        const float lam = 0.01f * (1.0f - p95);

        // A: r_sum[j] partial per warp from registers
        float part = 0.f;
#pragma unroll
        for (int i = 0; i < CH; i++) part += rs[i];
        if (ph == 0) pA[wid*16 + j] = part;
        __syncthreads();
        if (tid < 16) {
            float s = 0.f;
#pragma unroll
            for (int h = 0; h < NW; h++) s += pA[h*16 + tid];
            const float inv = 1.0f/(s + EPSR);
            srs[tid] = s; sinv[tid] = inv; sS[tid] = s*inv;
        }
        __syncthreads();

        // BC: moments from register votes
        {
            const float invj = sinv[j];
            float m[8], s2[8];
#pragma unroll
            for (int p = 0; p < 8; p++) { m[p] = 0.f; s2[p] = 0.f; }
#pragma unroll
            for (int i = 0; i < CH; i++) {
                const float c = rs[i] * invj;
#pragma unroll
                for (int p = 0; p < 8; p++) {
                    const float v = vr[i][p];
                    m[p]  = fmaf(c, v, m[p]);
                    s2[p] = fmaf(c, v*v, s2[p]);
                }
            }
            float* pm = pbm + wid*BBPS + j*16 + ph*8;
            float* ps = pbs + wid*BBPS + j*16 + ph*8;
            *(float4*)(pm)   = make_float4(m[0],m[1],m[2],m[3]);
            *(float4*)(pm+4) = make_float4(m[4],m[5],m[6],m[7]);
            *(float4*)(ps)   = make_float4(s2[0],s2[1],s2[2],s2[3]);
            *(float4*)(ps+4) = make_float4(s2[4],s2[5],s2[6],s2[7]);
        }
        __syncthreads();

        // Finalize + D: warp jj reduces partials over NW warps
        if (wid < 16) {
            const int jj = wid;
            float lg = 0.f;
            if (lane < 16) {
                const int idx = jj*16 + lane;
                float m = 0.f, s = 0.f;
#pragma unroll
                for (int h = 0; h < NW; h++) {
                    m += pbm[h*BBPS + idx];
                    s += pbs[h*BBPS + idx];
                }
                smu[idx] = m;
                const float sg = fmaxf(s - m*m*(2.0f - sS[jj]), 0.0f) + EPSR;
                ssg[idx] = 0.5f / sg;
                lg = __logf(sg);
            }
            float sl = lg;
#pragma unroll
            for (int d = 16; d; d >>= 1)
                sl += __shfl_xor_sync(0xffffffffu, sl, d);
            if (lane == 0) {
                const float cost = (16.0f*bu[jj] + 0.5f*sl) * srs[jj];
                const float ao = 1.0f / (1.0f + __expf(-lam*(ba[jj] - cost)));
                sao[jj]  = ao;
                sbia[jj] = -0.5f*(16.0f*LOG2PI + sl) + __logf(ao + EPSR);
            }
        }
        __syncthreads();

        // E: new r from register votes (r kept premultiplied by a_in)
        if (it < 2) {
            float muv[8], sgv[8];
            {
                const float4 a0 = *(const float4*)(smu + j*16 + ph*8);
                const float4 a1 = *(const float4*)(smu + j*16 + ph*8 + 4);
                const float4 b0 = *(const float4*)(ssg + j*16 + ph*8);
                const float4 b1 = *(const float4*)(ssg + j*16 + ph*8 + 4);
                muv[0]=a0.x; muv[1]=a0.y; muv[2]=a0.z; muv[3]=a0.w;
                muv[4]=a1.x; muv[5]=a1.y; muv[6]=a1.z; muv[7]=a1.w;
                sgv[0]=b0.x; sgv[1]=b0.y; sgv[2]=b0.z; sgv[3]=b0.w;
                sgv[4]=b1.x; sgv[5]=b1.y; sgv[6]=b1.z; sgv[7]=b1.w;
            }
            const float bia = sbia[j];
#pragma unroll
            for (int i = 0; i < CH; i++) {
                float q = 0.f;
#pragma unroll
                for (int p = 0; p < 8; p++) {
                    const float d = vr[i][p] - muv[p];
                    q = fmaf(d*d, sgv[p], q);
                }
                q += __shfl_xor_sync(0xffffffffu, q, 16);
                const float lnp = bia - q;
                float mx = lnp;
#pragma unroll
                for (int dd = 8; dd; dd >>= 1)
                    mx = fmaxf(mx, __shfl_xor_sync(0xffffffffu, mx, dd));
                const float e = __expf(lnp - mx);
                float se = e;
#pragma unroll
                for (int dd = 8; dd; dd >>= 1)
                    se += __shfl_xor_sync(0xffffffffu, se, dd);
                rs[i] = (e / se) * sa_s[k0 + i];
            }
            __syncthreads();
        }
    }
    __syncthreads();

    // Outputs (pose with fused BN, activations)
    for (int t = tid; t < BBPS; t += NT) {
        poseOut[(((size_t)n*BBPS + t)*OH + oy)*OH + ox] =
            smu[t]*BN_SCALE*bng[t] + bnb[t];
    }
    if (tid < 16)
        aOut[(((size_t)n*16 + tid)*OH + oy)*OH + ox] = sao[tid];
}

// ---------------------------------------------------------------------------
// EM routing v5 path (kept for EM3: BB=10 breaks the lane mapping).
// ---------------------------------------------------------------------------
template<int NT, int A_, int PS, int BB, int KS, int STR, int PD, int IH, int OH,
         int KSPLIT, bool WPOSE, bool FC>
__global__ __launch_bounds__(NT, 1)
void em_kernel(const float* __restrict__ aIn,
               const float* __restrict__ poseIn,
               const float* __restrict__ Wm,
               const float* __restrict__ bu,
               const float* __restrict__ ba,
               const float* __restrict__ bng,
               const float* __restrict__ bnb,
               float* __restrict__ aOut,
               float* __restrict__ poseOut)
{
    constexpr int KK   = KS*KS;
    constexpr int KKA  = KK*A_;
    constexpr int BBPS = BB*PS;
    constexpr int VST  = BBPS + 4;
    constexpr int RST  = BB + 1;
    constexpr int SPS  = PS;
    constexpr int NV4  = BBPS/4;
    constexpr int UNITS= KSPLIT*NV4;
    constexpr int CH   = KKA / KSPLIT;

    extern __shared__ float sm[];
    float* sv   = sm;
    float* pbm  = sv   + KKA*VST;
    float* pbs  = pbm  + KSPLIT*BBPS;
    float* smu  = pbs  + KSPLIT*BBPS;
    float* ssg  = smu  + BBPS;
    float* sr   = ssg  + BBPS;
    float* sa   = sr   + KKA*RST;
    float* srs  = sa   + KKA;
    float* sinv = srs  + BB;
    float* sS   = sinv + BB;
    float* sao  = sS   + BB;
    float* sbia = sao  + BB;
    float* spt  = pbm;

    const int lidx = blockIdx.x;
    const int oy = lidx / OH, ox = lidx % OH;
    const int n  = blockIdx.y;
    const int tid  = threadIdx.x;
    const int wid  = tid >> 5;
    const int lane = tid & 31;

    for (int t = tid; t < KKA*PS; t += NT) {
        const int k = t / PS, p = t % PS;
        const int kk = k / A_, ai = k % A_;
        const int ki = kk / KS, kj = kk % KS;
        const int iy = oy*STR + ki - PD, ix = ox*STR + kj - PD;
        float v = 0.f;
        if (iy >= 0 && iy < IH && ix >= 0 && ix < IH)
            v = poseIn[(((size_t)n*A_*PS + ai*PS + p)*IH + iy)*IH + ix];
        spt[k*SPS + p] = v;
    }
    for (int k = tid; k < KKA; k += NT) {
        const int kk = k / A_, ai = k % A_;
        const int ki = kk / KS, kj = kk % KS;
        const int iy = oy*STR + ki - PD, ix = ox*STR + kj - PD;
        float v = 0.f;
        if (iy >= 0 && iy < IH && ix >= 0 && ix < IH)
            v = aIn[(((size_t)n*A_ + ai)*IH + iy)*IH + ix];
        sa[k] = v;
    }
    __syncthreads();

    {
        constexpr int TOT = KKA*NV4;
        constexpr int TRIPS = (TOT + NT - 1) / NT;
#pragma unroll
        for (int tr = 0; tr < TRIPS; tr++) {
            const int t = tr*NT + tid;
            const bool act = (t < TOT);
            const int k = act ? t / NV4 : 0;
            const int r4 = act ? t % NV4 : 0;
            const int j = r4 >> 2, xi = lane & 3;
            float4 p4 = make_float4(0,0,0,0), w4 = make_float4(0,0,0,0);
            if (act) {
                p4 = *(const float4*)(spt + k*SPS + xi*4);
                w4 = *(const float4*)(Wm + ((size_t)k*BB + j)*16 + xi*4);
            }
            float4 acc; acc.x = acc.y = acc.z = acc.w = 0.f;
            const int base = lane & ~3;
#pragma unroll
            for (int y = 0; y < 4; y++) {
                const float py = (y==0) ? p4.x : (y==1) ? p4.y : (y==2) ? p4.z : p4.w;
                float4 wy;
                wy.x = __shfl_sync(0xffffffffu, w4.x, base + y);
                wy.y = __shfl_sync(0xffffffffu, w4.y, base + y);
                wy.z = __shfl_sync(0xffffffffu, w4.z, base + y);
                wy.w = __shfl_sync(0xffffffffu, w4.w, base + y);
                acc.x = fmaf(py, wy.x, acc.x);
                acc.y = fmaf(py, wy.y, acc.y);
                acc.z = fmaf(py, wy.z, acc.z);
                acc.w = fmaf(py, wy.w, acc.w);
            }
            if (act) *(float4*)(sv + k*VST + r4*4) = acc;
        }
    }
    for (int t = tid; t < KKA*BB; t += NT)
        sr[(t/BB)*RST + (t%BB)] = 1.0f / (float)BB;
    __syncthreads();

    float p95 = 1.0f;
    for (int it = 0; it < 3; it++) {
        p95 *= 0.95f;
        const float lam = 0.01f * (1.0f - p95);

        if (wid < BB) {
            float s = 0.f;
            for (int k = lane; k < KKA; k += 32)
                s = fmaf(sr[k*RST + wid], sa[k], s);
#pragma unroll
            for (int d = 16; d; d >>= 1)
                s += __shfl_xor_sync(0xffffffffu, s, d);
            if (lane == 0) {
                const float inv = 1.0f/(s + EPSR);
                srs[wid] = s; sinv[wid] = inv; sS[wid] = s*inv;
            }
        }
        __syncthreads();

        if (tid < UNITS) {
            const int h = tid / NV4, r4 = tid % NV4;
            const int j = r4 >> 2;
            const int k0 = h*CH;
            const float invj = sinv[j];
            float4 m; m.x=m.y=m.z=m.w=0.f;
            float4 s; s.x=s.y=s.z=s.w=0.f;
#pragma unroll 4
            for (int i = 0; i < CH; i++) {
                const int k = k0 + i;
                const float c = sr[k*RST + j] * sa[k] * invj;
                const float4 v = *(const float4*)(sv + k*VST + r4*4);
                m.x = fmaf(c, v.x, m.x); s.x = fmaf(c, v.x*v.x, s.x);
                m.y = fmaf(c, v.y, m.y); s.y = fmaf(c, v.y*v.y, s.y);
                m.z = fmaf(c, v.z, m.z); s.z = fmaf(c, v.z*v.z, s.z);
                m.w = fmaf(c, v.w, m.w); s.w = fmaf(c, v.w*v.w, s.w);
            }
            *(float4*)(pbm + h*BBPS + r4*4) = m;
            *(float4*)(pbs + h*BBPS + r4*4) = s;
        }
        __syncthreads();

        if (wid < BB) {
            const int j = wid;
            float lg = 0.f;
            if (lane < PS) {
                const int idx = j*PS + lane;
                float m = 0.f, s = 0.f;
#pragma unroll
                for (int h = 0; h < KSPLIT; h++) {
                    m += pbm[h*BBPS + idx];
                    s += pbs[h*BBPS + idx];
                }
                smu[idx] = m;
                float sg = fmaxf(s - m*m*(2.0f - sS[j]), 0.0f) + EPSR;
                ssg[idx] = 0.5f / sg;
                lg = __logf(sg);
            }
            float sl = lg;
#pragma unroll
            for (int d = 16; d; d >>= 1)
                sl += __shfl_xor_sync(0xffffffffu, sl, d);
            if (lane == 0) {
                const float cost = ((float)PS*bu[j] + 0.5f*sl) * srs[j];
                const float ao = 1.0f / (1.0f + __expf(-lam*(ba[j] - cost)));
                sao[j]  = ao;
                sbia[j] = -0.5f*((float)PS*LOG2PI + sl) + __logf(ao + EPSR);
            }
        }
        __syncthreads();

        if (it < 2) {
            const int j1 = lane >> 2;
            const bool act2 = (lane + 32 < NV4);
            const int j2 = (lane + 32) >> 2;
            float4 ma = *(const float4*)(smu + lane*4);
            float4 ga = *(const float4*)(ssg + lane*4);
            const float bia1 = sbia[j1];
            float4 mb, gb; float bia2 = 0.f;
            if (act2) {
                mb = *(const float4*)(smu + (lane+32)*4);
                gb = *(const float4*)(ssg + (lane+32)*4);
                bia2 = sbia[j2];
            }
#pragma unroll 2
            for (int k = wid; k < KKA; k += NT/32) {
                const float* vk = sv + k*VST;
                float4 va = *(const float4*)(vk + lane*4);
                float d, qa = 0.f;
                d = va.x-ma.x; qa = fmaf(d*d, ga.x, qa);
                d = va.y-ma.y; qa = fmaf(d*d, ga.y, qa);
                d = va.z-ma.z; qa = fmaf(d*d, ga.z, qa);
                d = va.w-ma.w; qa = fmaf(d*d, ga.w, qa);
                float qb = 0.f;
                if (act2) {
                    float4 vb = *(const float4*)(vk + (lane+32)*4);
                    d = vb.x-mb.x; qb = fmaf(d*d, gb.x, qb);
                    d = vb.y-mb.y; qb = fmaf(d*d, gb.y, qb);
                    d = vb.z-mb.z; qb = fmaf(d*d, gb.z, qb);
                    d = vb.w-mb.w; qb = fmaf(d*d, gb.w, qb);
                }
                qa += __shfl_xor_sync(0xffffffffu, qa, 1);
                qa += __shfl_xor_sync(0xffffffffu, qa, 2);
                qb += __shfl_xor_sync(0xffffffffu, qb, 1);
                qb += __shfl_xor_sync(0xffffffffu, qb, 2);
                const float lnpa = bia1 - qa;
                const float lnpb = act2 ? bia2 - qb : -1e30f;
                float mx = fmaxf(lnpa, lnpb);
#pragma unroll
                for (int dd = 4; dd <= 16; dd <<= 1)
                    mx = fmaxf(mx, __shfl_xor_sync(0xffffffffu, mx, dd));
                const float ea = __expf(lnpa - mx);
                const float eb = act2 ? __expf(lnpb - mx) : 0.f;
                float se = ea + eb;
#pragma unroll
                for (int dd = 4; dd <= 16; dd <<= 1)
                    se += __shfl_xor_sync(0xffffffffu, se, dd);
                const float inv = 1.0f / se;
                if ((lane & 3) == 0) {
                    sr[k*RST + j1] = ea * inv;
                    if (act2) sr[k*RST + j2] = eb * inv;
                }
            }
            __syncthreads();
        }
    }
    __syncthreads();

    if (WPOSE) {
        for (int t = tid; t < BBPS; t += NT) {
            poseOut[(((size_t)n*BBPS + t)*OH + oy)*OH + ox] =
                smu[t]*BN_SCALE*bng[t] + bnb[t];
        }
    }
    if (tid < BB) {
        if (FC)
            aOut[((size_t)n*(OH*OH) + lidx)*BB + tid] = sao[tid];
        else
            aOut[(((size_t)n*BB + tid)*OH + oy)*OH + ox] = sao[tid];
    }
}

// ---------------------------------------------------------------------------
__global__ void reduce_kernel(const float* __restrict__ afc, float* __restrict__ out)
{
    const int t = blockIdx.x*blockDim.x + threadIdx.x;
    if (t < 320) {
        const int n = t / 10, j = t % 10;
        float s = 0.f;
        for (int l = 0; l < 25; l++) s += afc[(n*25 + l)*10 + j];
        out[t] = s * (1.0f/25.0f);
    }
}

// ---------------------------------------------------------------------------
extern "C" void kernel_launch(void* const* d_in, const int* in_sizes, int n_in,
                              void* d_out, int out_size)
{
    const float* x       = (const float*)d_in[0];
    const float* conv1_w = (const float*)d_in[1];
    const float* bn1_g   = (const float*)d_in[2];
    const float* bn1_b   = (const float*)d_in[3];
    const float* conva_w = (const float*)d_in[4];
    const float* bna_g   = (const float*)d_in[5];
    const float* bna_b   = (const float*)d_in[6];
    const float* convp_w = (const float*)d_in[7];
    const float* bnp_g   = (const float*)d_in[8];
    const float* bnp_b   = (const float*)d_in[9];
    const float* W1      = (const float*)d_in[10];
    const float* bu1     = (const float*)d_in[11];
    const float* ba1     = (const float*)d_in[12];
    const float* bnc1_g  = (const float*)d_in[13];
    const float* bnc1_b  = (const float*)d_in[14];
    const float* W2      = (const float*)d_in[15];
    const float* bu2     = (const float*)d_in[16];
    const float* ba2     = (const float*)d_in[17];
    const float* bnc2_g  = (const float*)d_in[18];
    const float* bnc2_b  = (const float*)d_in[19];
    const float* Wfc     = (const float*)d_in[20];
    const float* bufc    = (const float*)d_in[21];
    const float* bafc    = (const float*)d_in[22];

    float *buf1, *bufA, *bufP, *bufA2, *bufP2, *bufA3, *bufP3, *bufFC;
    cudaGetSymbolAddress((void**)&buf1,  g_buf1);
    cudaGetSymbolAddress((void**)&bufA,  g_bufA);
    cudaGetSymbolAddress((void**)&bufP,  g_bufP);
    cudaGetSymbolAddress((void**)&bufA2, g_bufA2);
    cudaGetSymbolAddress((void**)&bufP2, g_bufP2);
    cudaGetSymbolAddress((void**)&bufA3, g_bufA3);
    cudaGetSymbolAddress((void**)&bufP3, g_bufP3);
    cudaGetSymbolAddress((void**)&bufFC, g_bufFC);

    // conv1 + bn
    conv1_kernel<<<dim3(32,16), 224>>>(x, conv1_w, bn1_g, bn1_b, buf1);

    // conva (sigmoid) + convp
    const size_t c3smem = 64*196*sizeof(float);
    cudaFuncSetAttribute((const void*)conv3_kernel<true,1>,  cudaFuncAttributeMaxDynamicSharedMemorySize, (int)c3smem);
    cudaFuncSetAttribute((const void*)conv3_kernel<false,2>, cudaFuncAttributeMaxDynamicSharedMemorySize, (int)c3smem);
    conv3_kernel<true,1 ><<<dim3(32,1), 192, c3smem>>>(buf1, conva_w, bna_g, bna_b, bufA, 256, 16);
    conv3_kernel<false,2><<<dim3(32,8), 192, c3smem>>>(buf1, convp_w, bnp_g, bnp_b, bufP, 256, 256);

    // EM1: 12x12 -> 6x6, k=3 s=2 p=1, A=16 B=16 (register votes, bnc1 fused)
    em_reg_kernel<576,16,3,2,1,12,6><<<dim3(36,32), 576>>>(
        bufA, bufP, W1, bu1, ba1, bnc1_g, bnc1_b, bufA2, bufP2);

    // EM2: 6x6 -> 6x6, k=3 s=1 p=1, A=16 B=16 (register votes, bnc2 fused)
    em_reg_kernel<576,16,3,1,1,6,6><<<dim3(36,32), 576>>>(
        bufA2, bufP2, W2, bu2, ba2, bnc2_g, bnc2_b, bufA3, bufP3);

    // EM3 (class caps): 6x6 -> 5x5, k=4 s=1 p=1, A=16 B=10 (smem votes)
    {
        constexpr int KKA = 256, BBPS = 160, VST = 164, RST = 11, KSP = 16;
        const size_t sm3 = (size_t)(KKA*VST + 2*KSP*BBPS + 2*BBPS
                                    + KKA*RST + KKA + 5*10) * sizeof(float);
        auto fn = em_kernel<768,16,16,10,4,1,1,6,5,KSP,false,true>;
        cudaFuncSetAttribute(fn, cudaFuncAttributeMaxDynamicSharedMemorySize, (int)sm3);
        fn<<<dim3(25,32), 768, sm3>>>(bufA3, bufP3, Wfc, bufc, bafc, nullptr, nullptr, bufFC, nullptr);
    }

    // mean over spatial
    reduce_kernel<<<1, 320>>>(bufFC, (float*)d_out);
}